// round 1
// baseline (speedup 1.0000x reference)
#include <cuda_runtime.h>
#include <cstdint>

#define SLEN 1024
#define BSZ  16
#define IND  256
#define NH   8
#define DH   32
#define PROJ 776              // NH*(3*DH+1)
#define NTOK (SLEN*BSZ)       // 16384
#define NCHAIN (BSZ*NH)       // 128
#define FW_ELEMS (NCHAIN*DH*DH)

// Scratch (static device globals; no runtime allocation)
__device__ float g_normed[(size_t)NTOK*IND];
__device__ float g_qkvb[(size_t)NTOK*PROJ];
__device__ float g_oseq[(size_t)NTOK*IND];

// ---------------------------------------------------------------------------
// LayerNorm: one block (256 threads) per token row
// ---------------------------------------------------------------------------
__global__ void ln_kernel(const float* __restrict__ x,
                          const float* __restrict__ gamma,
                          const float* __restrict__ beta)
{
    int row = blockIdx.x;
    int tid = threadIdx.x;
    float v = x[(size_t)row * IND + tid];
    float s = v, s2 = v * v;
#pragma unroll
    for (int o = 16; o > 0; o >>= 1) {
        s  += __shfl_xor_sync(0xffffffffu, s,  o);
        s2 += __shfl_xor_sync(0xffffffffu, s2, o);
    }
    __shared__ float sh[2][8];
    int w = tid >> 5, l = tid & 31;
    if (l == 0) { sh[0][w] = s; sh[1][w] = s2; }
    __syncthreads();
    float ts = 0.f, ts2 = 0.f;
#pragma unroll
    for (int i = 0; i < 8; i++) { ts += sh[0][i]; ts2 += sh[1][i]; }
    float mu  = ts * (1.0f / IND);
    float var = ts2 * (1.0f / IND) - mu * mu;
    float r   = rsqrtf(var + 1e-5f);
    g_normed[(size_t)row * IND + tid] = (v - mu) * r * gamma[tid] + beta[tid];
}

// ---------------------------------------------------------------------------
// Tiled NT GEMM: C[M,N] = A[M,K] * B[N,K]^T (+ resid), all row-major fp32
// Block 64x64, BK=32, 256 threads, 4x4 microtile
// ---------------------------------------------------------------------------
#define BMv 64
#define BNv 64
#define BKv 32

__global__ __launch_bounds__(256)
void gemm_nt(const float* __restrict__ A, const float* __restrict__ B,
             float* __restrict__ C, int M, int N, int K,
             const float* __restrict__ resid)
{
    __shared__ float As[BMv][BKv + 1];
    __shared__ float Bs[BNv][BKv + 1];

    int bm = blockIdx.x * BMv;
    int bn = blockIdx.y * BNv;
    int tid = threadIdx.x;
    int tx = tid & 15, ty = tid >> 4;

    float acc[4][4];
#pragma unroll
    for (int i = 0; i < 4; i++)
#pragma unroll
        for (int j = 0; j < 4; j++) acc[i][j] = 0.f;

    for (int k0 = 0; k0 < K; k0 += BKv) {
#pragma unroll
        for (int i = 0; i < 2; i++) {
            int idx = tid + i * 256;
            int r = idx >> 3, c = (idx & 7) * 4;
            float4 va = *(const float4*)(A + (size_t)(bm + r) * K + k0 + c);
            As[r][c + 0] = va.x; As[r][c + 1] = va.y;
            As[r][c + 2] = va.z; As[r][c + 3] = va.w;
            float4 vb = make_float4(0.f, 0.f, 0.f, 0.f);
            if (bn + r < N)
                vb = *(const float4*)(B + (size_t)(bn + r) * K + k0 + c);
            Bs[r][c + 0] = vb.x; Bs[r][c + 1] = vb.y;
            Bs[r][c + 2] = vb.z; Bs[r][c + 3] = vb.w;
        }
        __syncthreads();
#pragma unroll
        for (int kk = 0; kk < BKv; kk++) {
            float a0 = As[ty * 4 + 0][kk];
            float a1 = As[ty * 4 + 1][kk];
            float a2 = As[ty * 4 + 2][kk];
            float a3 = As[ty * 4 + 3][kk];
            float b0 = Bs[tx * 4 + 0][kk];
            float b1 = Bs[tx * 4 + 1][kk];
            float b2 = Bs[tx * 4 + 2][kk];
            float b3 = Bs[tx * 4 + 3][kk];
            acc[0][0] = fmaf(a0, b0, acc[0][0]); acc[0][1] = fmaf(a0, b1, acc[0][1]);
            acc[0][2] = fmaf(a0, b2, acc[0][2]); acc[0][3] = fmaf(a0, b3, acc[0][3]);
            acc[1][0] = fmaf(a1, b0, acc[1][0]); acc[1][1] = fmaf(a1, b1, acc[1][1]);
            acc[1][2] = fmaf(a1, b2, acc[1][2]); acc[1][3] = fmaf(a1, b3, acc[1][3]);
            acc[2][0] = fmaf(a2, b0, acc[2][0]); acc[2][1] = fmaf(a2, b1, acc[2][1]);
            acc[2][2] = fmaf(a2, b2, acc[2][2]); acc[2][3] = fmaf(a2, b3, acc[2][3]);
            acc[3][0] = fmaf(a3, b0, acc[3][0]); acc[3][1] = fmaf(a3, b1, acc[3][1]);
            acc[3][2] = fmaf(a3, b2, acc[3][2]); acc[3][3] = fmaf(a3, b3, acc[3][3]);
        }
        __syncthreads();
    }

#pragma unroll
    for (int i = 0; i < 4; i++) {
        int m = bm + ty * 4 + i;
#pragma unroll
        for (int j = 0; j < 4; j++) {
            int n = bn + tx * 4 + j;
            if (n < N) {
                float v = acc[i][j];
                if (resid) v += resid[(size_t)m * N + n];
                C[(size_t)m * N + n] = v;
            }
        }
    }
}

// ---------------------------------------------------------------------------
// Delta-rule recurrence: one warp per (batch, head) chain.
// Thread `lane` owns row `lane` of the 32x32 fast-weight matrix (in regs).
// o_t = W_old q + delta * (k.q),  W += delta k^T  (delta = beta*(v - W_old k))
// ---------------------------------------------------------------------------
__global__ __launch_bounds__(32)
void rec_kernel(const float* __restrict__ state,
                float* __restrict__ out_fw, int write_fw)
{
    int chain = blockIdx.x;            // 0..127
    int b = chain >> 3, h = chain & 7;
    int lane = threadIdx.x;

    float W[DH];
    const float* st = state + ((size_t)chain * DH + lane) * DH;
#pragma unroll
    for (int j = 0; j < DH; j++) W[j] = st[j];

    __shared__ __align__(16) float sk[2][DH];
    __shared__ __align__(16) float sq[2][DH];

    const float* base = g_qkvb + (size_t)b * PROJ + (size_t)h * 97;

    // prefetch t = 0
    float qc = base[lane], kc = base[32 + lane], vc = base[64 + lane], bc = base[96];

    for (int t = 0; t < SLEN; t++) {
        // prefetch t+1 (hidden under this step's compute)
        float qn = 0.f, kn = 0.f, vn = 0.f, bn2 = 0.f;
        if (t + 1 < SLEN) {
            const float* nxt = base + (size_t)(t + 1) * BSZ * PROJ;
            qn = nxt[lane]; kn = nxt[32 + lane]; vn = nxt[64 + lane]; bn2 = nxt[96];
        }

        // activations: elu(x)+1, normalized over head dim; sigmoid(beta)
        float eq = qc > 0.f ? qc + 1.f : __expf(qc);
        float ek = kc > 0.f ? kc + 1.f : __expf(kc);
        float sumq = eq, sumk = ek;
#pragma unroll
        for (int o = 16; o > 0; o >>= 1) {
            sumq += __shfl_xor_sync(0xffffffffu, sumq, o);
            sumk += __shfl_xor_sync(0xffffffffu, sumk, o);
        }
        float qv = eq / (sumq + 1e-5f);
        float kv = ek / (sumk + 1e-5f);
        float beta = 1.f / (1.f + __expf(-bc));

        int bufi = t & 1;
        sk[bufi][lane] = kv;
        sq[bufi][lane] = qv;
        __syncwarp();

        float kq = kv * qv;
#pragma unroll
        for (int o = 16; o > 0; o >>= 1) kq += __shfl_xor_sync(0xffffffffu, kq, o);

        float kkreg[DH];
        float v0 = 0.f, v1 = 0.f, w0 = 0.f, w1 = 0.f;
#pragma unroll
        for (int j4 = 0; j4 < DH / 4; j4++) {
            float4 k4 = *(const float4*)&sk[bufi][j4 * 4];
            float4 q4 = *(const float4*)&sq[bufi][j4 * 4];
            kkreg[j4 * 4 + 0] = k4.x; kkreg[j4 * 4 + 1] = k4.y;
            kkreg[j4 * 4 + 2] = k4.z; kkreg[j4 * 4 + 3] = k4.w;
            v0 = fmaf(W[j4 * 4 + 0], k4.x, v0);
            v1 = fmaf(W[j4 * 4 + 1], k4.y, v1);
            v0 = fmaf(W[j4 * 4 + 2], k4.z, v0);
            v1 = fmaf(W[j4 * 4 + 3], k4.w, v1);
            w0 = fmaf(W[j4 * 4 + 0], q4.x, w0);
            w1 = fmaf(W[j4 * 4 + 1], q4.y, w1);
            w0 = fmaf(W[j4 * 4 + 2], q4.z, w0);
            w1 = fmaf(W[j4 * 4 + 3], q4.w, w1);
        }
        float v_old = v0 + v1;
        float wq    = w0 + w1;

        float delta = beta * (vc - v_old);
        float o_out = fmaf(delta, kq, wq);
#pragma unroll
        for (int j = 0; j < DH; j++) W[j] = fmaf(delta, kkreg[j], W[j]);

        g_oseq[((size_t)t * BSZ + b) * IND + h * DH + lane] = o_out;

        qc = qn; kc = kn; vc = vn; bc = bn2;
    }

    if (write_fw) {
        float* fw = out_fw + ((size_t)chain * DH + lane) * DH;
#pragma unroll
        for (int j = 0; j < DH; j++) fw[j] = W[j];
    }
}

// ---------------------------------------------------------------------------
extern "C" void kernel_launch(void* const* d_in, const int* in_sizes, int n_in,
                              void* d_out, int out_size)
{
    const float* x        = (const float*)d_in[0];
    const float* state    = (const float*)d_in[1];
    const float* W_slow   = (const float*)d_in[2];
    const float* ln_gamma = (const float*)d_in[3];
    const float* ln_beta  = (const float*)d_in[4];
    const float* W_out    = (const float*)d_in[5];
    float* out = (float*)d_out;

    float* normed; cudaGetSymbolAddress((void**)&normed, g_normed);
    float* qkvb;   cudaGetSymbolAddress((void**)&qkvb,   g_qkvb);
    float* oseq;   cudaGetSymbolAddress((void**)&oseq,   g_oseq);

    // 1) LayerNorm
    ln_kernel<<<NTOK, IND>>>(x, ln_gamma, ln_beta);

    // 2) qkvb = normed @ W_slow^T   [16384 x 776]
    dim3 gB(NTOK / BMv, (PROJ + BNv - 1) / BNv);
    gemm_nt<<<gB, 256>>>(normed, W_slow, qkvb, NTOK, PROJ, IND, nullptr);

    // 3) delta-rule recurrence (writes g_oseq and final fast weights)
    int write_fw = (out_size >= (int)((size_t)NTOK * IND + FW_ELEMS)) ? 1 : 0;
    rec_kernel<<<NCHAIN, DH>>>(state, out + (size_t)NTOK * IND, write_fw);

    // 4) out = x + oseq @ W_out^T   [16384 x 256]
    dim3 gD(NTOK / BMv, (IND + BNv - 1) / BNv);
    gemm_nt<<<gD, 256>>>(oseq, W_out, out, NTOK, IND, IND, x);
}